// round 1
// baseline (speedup 1.0000x reference)
#include <cuda_runtime.h>
#include <cstdint>

#define BB 8
#define NN 2048
#define FIN 128
#define FOUT 64

// ---- scratch (static device allocations are allowed) ----
__device__ float    g_h[BB * NN * FOUT];          // 4 MB
__device__ float    g_f1[BB * NN];
__device__ float    g_f2[BB * NN];
__device__ unsigned g_adj[BB * NN * (NN / 32)];   // 4 MB bitmask

// ---------------------------------------------------------------------------
// packed f32x2 helpers (Blackwell FFMA2)
// ---------------------------------------------------------------------------
__device__ __forceinline__ unsigned long long fma2(unsigned long long a,
                                                   unsigned long long b,
                                                   unsigned long long c) {
    unsigned long long d;
    asm("fma.rn.f32x2 %0, %1, %2, %3;" : "=l"(d) : "l"(a), "l"(b), "l"(c));
    return d;
}
__device__ __forceinline__ unsigned long long add2(unsigned long long a,
                                                   unsigned long long b) {
    unsigned long long d;
    asm("add.rn.f32x2 %0, %1, %2;" : "=l"(d) : "l"(a), "l"(b));
    return d;
}

// ---------------------------------------------------------------------------
// Kernel A: h = x @ W, f1 = h @ a[:64], f2 = h @ a[64:]
// block = 256 threads, 64 rows per block. lane owns a feature PAIR (2*lane,
// 2*lane+1) so one warp spans all 64 features of a row -> pure shuffle reduce.
// ---------------------------------------------------------------------------
__global__ __launch_bounds__(256) void k_proj(const float* __restrict__ x,
                                              const float* __restrict__ W,
                                              const float* __restrict__ a) {
    __shared__ float Ws[FIN * FOUT];   // 32 KB
    __shared__ float xs[8][FIN];       // 4 KB
    const int tid  = threadIdx.x;
    const int lane = tid & 31;
    const int rg   = tid >> 5;         // 0..7 (row within group of 8)

    for (int l = tid; l < FIN * FOUT; l += 256) Ws[l] = W[l];
    const float2 av1 = *(const float2*)(a + 2 * lane);
    const float2 av2 = *(const float2*)(a + FOUT + 2 * lane);

    const int row0 = blockIdx.x * 64;
    for (int it = 0; it < 8; ++it) {
        __syncthreads();   // also covers Ws on it==0, guards xs reuse after
        const float* src = x + (size_t)(row0 + it * 8) * FIN;
        for (int l = tid; l < 8 * FIN; l += 256) xs[l >> 7][l & 127] = src[l];
        __syncthreads();

        const int row = row0 + it * 8 + rg;
        float acc0 = 0.f, acc1 = 0.f;
#pragma unroll
        for (int k = 0; k < FIN; ++k) {
            const float  xv = xs[rg][k];
            const float2 wv = *(const float2*)(Ws + k * FOUT + 2 * lane);
            acc0 = fmaf(xv, wv.x, acc0);
            acc1 = fmaf(xv, wv.y, acc1);
        }
        *(float2*)(g_h + (size_t)row * FOUT + 2 * lane) = make_float2(acc0, acc1);

        float p1 = acc0 * av1.x + acc1 * av1.y;
        float p2 = acc0 * av2.x + acc1 * av2.y;
#pragma unroll
        for (int d = 16; d; d >>= 1) {
            p1 += __shfl_xor_sync(0xffffffffu, p1, d);
            p2 += __shfl_xor_sync(0xffffffffu, p2, d);
        }
        if (lane == 0) { g_f1[row] = p1; g_f2[row] = p2; }
    }
}

// ---------------------------------------------------------------------------
// Kernel B: pack adj (int32, 134 MB) -> bitmask (4.2 MB). Each warp handles
// 128 consecutive elements via 4 coalesced ballots.
// ---------------------------------------------------------------------------
__global__ __launch_bounds__(256) void k_pack(const int* __restrict__ adj) {
    const int gwarp = (int)((blockIdx.x * blockDim.x + threadIdx.x) >> 5);
    const int lane  = threadIdx.x & 31;
    const size_t e0 = (size_t)gwarp * 128;
#pragma unroll
    for (int c = 0; c < 4; ++c) {
        const int v = adj[e0 + c * 32 + lane];
        const unsigned m = __ballot_sync(0xffffffffu, v > 0);
        if (lane == 0) g_adj[gwarp * 4 + c] = m;
    }
}

// ---------------------------------------------------------------------------
// Kernel C: fused masked attention + PV accumulation + ELU.
// Grid (NN/64, BB); block 256 = 64 rows x 4 j-split groups (512 j each).
// h tiles (32 j-rows x 64 f) per group staged in smem; j loop is warp-uniform
// so every h read is a broadcast LDS.128. Accumulation in packed f32x2.
// ---------------------------------------------------------------------------
#define JTILE   32
#define NPASS   16          // 512 / 32
#define SBUF_FLOATS (4 * JTILE * FOUT + NN)   // 8192 + 2048 = 40 KB

__global__ void __launch_bounds__(256, 2)
k_attn(float* __restrict__ out) {
    __shared__ float sbuf[SBUF_FLOATS];
    float* h_s  = sbuf;               // 4 tiles * 32 * 64 floats
    float* f2_s = sbuf + 4 * JTILE * FOUT;

    const int tid = threadIdx.x;
    const int g   = tid >> 6;          // j-split group 0..3
    const int r   = tid & 63;          // row within block
    const int b   = blockIdx.y;
    const int i   = blockIdx.x * 64 + r;

    const float* f2b = g_f2 + b * NN;
    for (int l = tid; l < NN; l += 256) f2_s[l] = f2b[l];

    const float     f1i  = g_f1[b * NN + i];
    const unsigned* arow = g_adj + (size_t)(b * NN + i) * (NN / 32) + g * NPASS;
    const float*    hb   = g_h + (size_t)b * NN * FOUT;

    unsigned long long acc[FOUT / 2];
#pragma unroll
    for (int k = 0; k < FOUT / 2; ++k) acc[k] = 0ull;
    float denom = 0.f;

    for (int pass = 0; pass < NPASS; ++pass) {
        __syncthreads();
        // cooperative load of all 4 group tiles: 2048 float4, 8 per thread
#pragma unroll
        for (int l = 0; l < 8; ++l) {
            const int e    = tid + l * 256;
            const int tile = e >> 9;          // 512 float4 per tile
            const int off  = e & 511;
            const float4 v = *(const float4*)(hb +
                (size_t)((tile * 512 + pass * JTILE + (off >> 4)) * FOUT) + (off & 15) * 4);
            *(float4*)(h_s + tile * (JTILE * FOUT) + off * 4) = v;
        }
        __syncthreads();

        const unsigned word      = arow[pass];
        const float*   f2p       = f2_s + g * 512 + pass * JTILE;
        const float*   hrow_base = h_s + g * (JTILE * FOUT);

#pragma unroll 4
        for (int j = 0; j < JTILE; ++j) {
            const unsigned bit = (word >> j) & 1u;
            const float s  = f1i + f2p[j];
            const float e2 = __expf(s + s);
            const float t  = 1.0f - __fdividef(2.0f, e2 + 1.0f);   // tanh(s)
            float w = __expf(t);
            w = bit ? w : 0.0f;
            denom += w;
            unsigned long long w2;
            asm("mov.b64 %0, {%1, %1};" : "=l"(w2) : "f"(w));
            const ulonglong2* hp = (const ulonglong2*)(hrow_base + j * FOUT);
#pragma unroll
            for (int k = 0; k < FOUT / 4; ++k) {
                const ulonglong2 p = hp[k];
                acc[2 * k]     = fma2(w2, p.x, acc[2 * k]);
                acc[2 * k + 1] = fma2(w2, p.y, acc[2 * k + 1]);
            }
        }
    }

    // ---- cross-group tree reduction through smem (reuses sbuf) ----
    __syncthreads();
    unsigned long long* stg = (unsigned long long*)sbuf;
    const int PITCH = 33;   // 32 acc pairs + denom word

    if (g >= 2) {
        unsigned long long* dst = stg + ((size_t)((g - 2) * 64 + r)) * PITCH;
#pragma unroll
        for (int k = 0; k < 32; ++k) dst[k] = acc[k];
        ((float*)(dst + 32))[0] = denom;
    }
    __syncthreads();
    if (g < 2) {
        const unsigned long long* src = stg + ((size_t)(g * 64 + r)) * PITCH;
#pragma unroll
        for (int k = 0; k < 32; ++k) acc[k] = add2(acc[k], src[k]);
        denom += ((const float*)(src + 32))[0];
    }
    __syncthreads();
    if (g == 1) {
        unsigned long long* dst = stg + (size_t)r * PITCH;
#pragma unroll
        for (int k = 0; k < 32; ++k) dst[k] = acc[k];
        ((float*)(dst + 32))[0] = denom;
    }
    __syncthreads();
    if (g == 0) {
        const unsigned long long* src = stg + (size_t)r * PITCH;
        const float dtot = denom + ((const float*)(src + 32))[0];
        const float inv  = 1.0f / dtot;
        float* op = out + (size_t)(b * NN + i) * FOUT;
#pragma unroll
        for (int k = 0; k < 32; ++k) {
            const unsigned long long d = add2(acc[k], src[k]);
            float lo, hi;
            asm("mov.b64 {%0, %1}, %2;" : "=f"(lo), "=f"(hi) : "l"(d));
            lo *= inv; hi *= inv;
            lo = lo > 0.f ? lo : expm1f(lo);
            hi = hi > 0.f ? hi : expm1f(hi);
            *(float2*)(op + 2 * k) = make_float2(lo, hi);
        }
    }
}

// ---------------------------------------------------------------------------
extern "C" void kernel_launch(void* const* d_in, const int* in_sizes, int n_in,
                              void* d_out, int out_size) {
    const float* x   = (const float*)d_in[0];
    const int*   adj = (const int*)d_in[1];
    const float* W   = (const float*)d_in[2];
    const float* a   = (const float*)d_in[3];
    float*       out = (float*)d_out;

    k_proj<<<BB * NN / 64, 256>>>(x, W, a);
    k_pack<<<(BB * NN * NN) / (128 * 8), 256>>>(adj);
    k_attn<<<dim3(NN / 64, BB), 256>>>(out);
}